// round 13
// baseline (speedup 1.0000x reference)
#include <cuda_runtime.h>
#include <math.h>

#define N_NODE  50000
#define N_EDGE  1000000
#define D_E     64
#define D_IN    128

// ---------------- device scratch (static; no allocations allowed) ----------------
__device__ float    g_hs[N_NODE * D_E];     // x_s @ W_src^T   (natural feature order)
__device__ float    g_ht[N_NODE * D_E];     // x_t @ W_tgt^T
__device__ float    g_as[N_NODE];           // hs . w_attn
__device__ float    g_at[N_NODE];           // ht . w_attn
__device__ float    g_v[D_E];               // W_edge^T @ w_attn
__device__ float    g_denom[N_NODE];        // softmax denominators per src
__device__ float    g_score[N_EDGE];        // post-leaky scores
// Pre-split bf16 hi/lo weight groups, pre-permuted (feature+k perms), bank-swizzled.
__device__ uint4    g_Wg[D_E * 16];         // W_edge  (K=64 : 16 groups/row)
__device__ uint4    g_Wsg[D_E * 32];        // W_src   (K=128: 32 groups/row)
__device__ uint4    g_Wtg[D_E * 32];        // W_tgt

// ---------------- helpers ----------------
__device__ __forceinline__ bool idx_is64(const void* p) {
    const long long* q = (const long long*)p;
    bool ok = true;
#pragma unroll
    for (int i = 0; i < 4; i++)
        ok = ok && ((unsigned long long)q[i] < (unsigned long long)N_NODE);
    return ok;
}
__device__ __forceinline__ int get_idx(const void* p, bool is64, size_t pos) {
    return is64 ? (int)((const long long*)p)[pos]
                : ((const int*)p)[pos];
}
// pack float pair -> bf16x2 hi plane + bf16x2 residual lo plane
__device__ __forceinline__ void bf16_split2(float x0, float x1, unsigned& hi, unsigned& lo) {
    unsigned h;
    asm("cvt.rn.bf16x2.f32 %0, %1, %2;" : "=r"(h) : "f"(x1), "f"(x0));
    float h0 = __uint_as_float(h << 16);
    float h1 = __uint_as_float(h & 0xFFFF0000u);
    unsigned l;
    asm("cvt.rn.bf16x2.f32 %0, %1, %2;" : "=r"(l) : "f"(x1 - h1), "f"(x0 - h0));
    hi = h; lo = l;
}
__device__ __forceinline__ void mma_bf16(float c[4], const unsigned a[4], unsigned b0, unsigned b1) {
    asm volatile(
        "mma.sync.aligned.m16n8k16.row.col.f32.bf16.bf16.f32 "
        "{%0,%1,%2,%3}, {%4,%5,%6,%7}, {%8,%9}, {%0,%1,%2,%3};"
        : "+f"(c[0]), "+f"(c[1]), "+f"(c[2]), "+f"(c[3])
        : "r"(a[0]), "r"(a[1]), "r"(a[2]), "r"(a[3]), "r"(b0), "r"(b1));
}
// feature permutation: logical MMA column n -> physical feature index.
__device__ __forceinline__ int fperm(int n) {
    return 16 * ((n >> 4) & 3) + 4 * ((n >> 1) & 3) + 2 * ((n >> 3) & 1) + (n & 1);
}

// ---------------- K0: prep — denoms, g_v, and ALL weight splits ----------------
__global__ void __launch_bounds__(256) prep_kernel(
    const float* __restrict__ W_src, const float* __restrict__ W_tgt,
    const float* __restrict__ W_edge, const float* __restrict__ w_attn) {
    int gid = blockIdx.x * blockDim.x + threadIdx.x;
    if (gid < N_NODE) g_denom[gid] = 0.f;
    if (gid < D_E) {
        float s = 0.f;
#pragma unroll 8
        for (int j = 0; j < D_E; j++) s += W_edge[j * D_E + gid] * w_attn[j];
        g_v[gid] = s;
    }
    if (gid < D_E * 16) {       // W_edge groups (K=64)
        int n = gid >> 4, r = gid & 15;
        int kt = r >> 2, tig = r & 3;
        const float* wr = W_edge + (size_t)fperm(n) * D_E + 16 * kt + 4 * tig;
        unsigned h0, l0, h1, l1;
        bf16_split2(wr[0], wr[1], h0, l0);
        bf16_split2(wr[2], wr[3], h1, l1);
        int slot = n * 16 + 4 * (kt ^ (n & 1)) + (tig ^ ((n >> 1) & 3));
        g_Wg[slot] = make_uint4(h0, h1, l0, l1);
    }
    if (gid < 2 * D_E * 32) {   // W_src / W_tgt groups (K=128)
        int which = gid >= D_E * 32;
        int i = gid - which * D_E * 32;
        int n = i >> 5, r = i & 31;
        int kt = r >> 2, tig = r & 3;
        const float* W = which ? W_tgt : W_src;
        const float* wr = W + (size_t)fperm(n) * D_IN + 16 * kt + 4 * tig;
        unsigned h0, l0, h1, l1;
        bf16_split2(wr[0], wr[1], h0, l0);
        bf16_split2(wr[2], wr[3], h1, l1);
        int slot = n * 32 + 4 * (kt ^ (n & 1)) + (tig ^ ((n >> 1) & 3));
        if (which) g_Wtg[slot] = make_uint4(h0, h1, l0, l1);
        else       g_Wsg[slot] = make_uint4(h0, h1, l0, l1);
    }
}

// ---------------- K1: node projections via bf16-split MMA ----------------
// 128 nodes x 64 feats per block, K=128 (8 k-steps). blockIdx.y: 0=src, 1=tgt.
__global__ void __launch_bounds__(256, 4) node_proj_mma(
    const float* __restrict__ x_s, const float* __restrict__ x_t,
    const float* __restrict__ w_attn) {
    __shared__ uint4 Wsh[D_E * 32];   // 32 KB

    const int tid  = threadIdx.x;
    const int lane = tid & 31, warp = tid >> 5;
    const int g = lane >> 2, tig = lane & 3;

    const float* x; float* hout; float* aout; const uint4* Wt;
    if (blockIdx.y == 0) { x = x_s; hout = g_hs; aout = g_as; Wt = g_Wsg; }
    else                 { x = x_t; hout = g_ht; aout = g_at; Wt = g_Wtg; }

    for (int i = tid; i < D_E * 32; i += 256) Wsh[i] = Wt[i];

    const int n0 = blockIdx.x * 128;
    const int nA = n0 + warp * 16 + g;
    const int nB = nA + 8;
    const bool vA = (nA < N_NODE), vB = (nB < N_NODE);
    const size_t rA = (size_t)(vA ? nA : (N_NODE - 1));
    const size_t rB = (size_t)(vB ? nB : (N_NODE - 1));

    const float4* pA = (const float4*)(x + rA * D_IN);
    const float4* pB = (const float4*)(x + rB * D_IN);
    // rolling prefetch, phys k = 16kt + 4tig
    float4 cura = __ldcs(&pA[tig]);
    float4 curb = __ldcs(&pB[tig]);

    __syncthreads();

    float c[8][4];
#pragma unroll
    for (int nt = 0; nt < 8; nt++)
#pragma unroll
        for (int r = 0; r < 4; r++) c[nt][r] = 0.f;

    const int bswz = (tig ^ ((g >> 1) & 3));
#pragma unroll
    for (int kt = 0; kt < 8; kt++) {
        float4 nxta, nxtb;
        if (kt < 7) {
            nxta = __ldcs(&pA[4 * (kt + 1) + tig]);
            nxtb = __ldcs(&pB[4 * (kt + 1) + tig]);
        }
        unsigned ah[4], al[4];
        bf16_split2(cura.x, cura.y, ah[0], al[0]);
        bf16_split2(curb.x, curb.y, ah[1], al[1]);
        bf16_split2(cura.z, cura.w, ah[2], al[2]);
        bf16_split2(curb.z, curb.w, ah[3], al[3]);
        const int koff = 4 * (kt ^ (g & 1)) + bswz;
#pragma unroll
        for (int nt = 0; nt < 8; nt++) {
            uint4 b = Wsh[(8 * nt + g) * 32 + koff];
            mma_bf16(c[nt], ah, b.x, b.y);   // Ah*Bh
            mma_bf16(c[nt], ah, b.z, b.w);   // Ah*Bl
            mma_bf16(c[nt], al, b.x, b.y);   // Al*Bh
        }
        cura = nxta; curb = nxtb;
    }

    // ---- epilogue: write rows + attn dot. Thread's chunk q = feats 16q+4tig..+3.
    float avA = 0.f, avB = 0.f;
    if (vA) {
        float4* op = (float4*)(hout + (size_t)nA * D_E);
#pragma unroll
        for (int q = 0; q < 4; q++) {
            float4 w = __ldg(&((const float4*)w_attn)[4 * q + tig]);
            float4 r = make_float4(c[2*q][0], c[2*q][1], c[2*q+1][0], c[2*q+1][1]);
            avA += r.x * w.x + r.y * w.y + r.z * w.z + r.w * w.w;
            op[4 * q + tig] = r;
        }
    }
    if (vB) {
        float4* op = (float4*)(hout + (size_t)nB * D_E);
#pragma unroll
        for (int q = 0; q < 4; q++) {
            float4 w = __ldg(&((const float4*)w_attn)[4 * q + tig]);
            float4 r = make_float4(c[2*q][2], c[2*q][3], c[2*q+1][2], c[2*q+1][3]);
            avB += r.x * w.x + r.y * w.y + r.z * w.z + r.w * w.w;
            op[4 * q + tig] = r;
        }
    }
    avA += __shfl_xor_sync(0xffffffffu, avA, 1);
    avB += __shfl_xor_sync(0xffffffffu, avB, 1);
    avA += __shfl_xor_sync(0xffffffffu, avA, 2);
    avB += __shfl_xor_sync(0xffffffffu, avB, 2);
    if (tig == 0) {
        if (vA) aout[nA] = avA;
        if (vB) aout[nB] = avB;
    }
}

// ---------------- K2: per-edge score + FUSED softmax denominator ----------------
// Default-policy loads (NOT __ldcs): the tail of ea stays L2-resident so the
// reversed-order out_kernel can reuse it.
__global__ void __launch_bounds__(256) score_kernel(
    const float* __restrict__ edge_attr, const void* __restrict__ eidx) {
    __shared__ float v[D_E];
    if (threadIdx.x < D_E) v[threadIdx.x] = g_v[threadIdx.x];
    __syncthreads();

    long long t = (long long)blockIdx.x * 256 + threadIdx.x;
    long long e = t >> 2;
    int q = (int)(t & 3);
    if (e >= N_EDGE) return;

    const float4* row = (const float4*)(edge_attr + e * D_E);
    float p = 0.f;
#pragma unroll
    for (int i = 0; i < 4; i++) {
        float4 av = row[q + 4 * i];
        float4 vv = *(const float4*)&v[4 * (q + 4 * i)];
        p += av.x * vv.x + av.y * vv.y + av.z * vv.z + av.w * vv.w;
    }
    p += __shfl_xor_sync(0xffffffffu, p, 1);
    p += __shfl_xor_sync(0xffffffffu, p, 2);
    if (q == 0) {
        bool is64 = idx_is64(eidx);
        int src = get_idx(eidx, is64, (size_t)e);
        int tgt = get_idx(eidx, is64, (size_t)N_EDGE + e);
        float s = p + g_as[src] + g_at[tgt];
        s = (s >= 0.f) ? s : 0.2f * s;
        g_score[e] = s;
        atomicAdd(&g_denom[src], __expf(s));
    }
}

// ---------------- K4: bf16-split tensor GEMM + gather + softmax + RMSNorm ----------------
// Blocks run in REVERSE edge order: the L2-resident tail of ea (left by
// score_kernel) is consumed first.
__global__ void __launch_bounds__(256, 4) out_kernel(
    const float* __restrict__ edge_attr, const void* __restrict__ eidx,
    const float* __restrict__ norm_w, float* __restrict__ out) {
    __shared__ uint4 Wg[D_E * 16];   // 16 KB

    const bool is64 = idx_is64(eidx);
    const int tid  = threadIdx.x;
    const int lane = tid & 31, warp = tid >> 5;
    const int g = lane >> 2, tig = lane & 3;

    for (int i = tid; i < D_E * 16; i += 256) Wg[i] = g_Wg[i];

    const long long e0 = (long long)(gridDim.x - 1 - blockIdx.x) * 128;
    const long long eA = e0 + warp * 16 + g;
    const long long eB = eA + 8;
    const bool vA = (eA < N_EDGE), vB = (eB < N_EDGE);
    const size_t rA = (size_t)(vA ? eA : (N_EDGE - 1));
    const size_t rB = (size_t)(vB ? eB : (N_EDGE - 1));

    // ---- prefetch epilogue metadata early (hide latency under MMA) ----
    const int sA = get_idx(eidx, is64, rA);
    const int tA = get_idx(eidx, is64, (size_t)N_EDGE + rA);
    const int sB = get_idx(eidx, is64, rB);
    const int tB = get_idx(eidx, is64, (size_t)N_EDGE + rB);
    float aAv = 0.f, aBv = 0.f;
    if (tig == 0) {
        aAv = __expf(g_score[rA]) / g_denom[sA];
        aBv = __expf(g_score[rB]) / g_denom[sB];
    }

    const float4* pA = (const float4*)(edge_attr + rA * D_E);
    const float4* pB = (const float4*)(edge_attr + rB * D_E);
    // rolling prefetch: stage kt=0
    float4 cura = __ldcs(&pA[tig]);
    float4 curb = __ldcs(&pB[tig]);

    const float alphaA = __shfl_sync(0xffffffffu, aAv, lane & 28);
    const float alphaB = __shfl_sync(0xffffffffu, aBv, lane & 28);

    __syncthreads();

    // ---- MMA mainloop ----
    float c[8][4];
#pragma unroll
    for (int nt = 0; nt < 8; nt++)
#pragma unroll
        for (int r = 0; r < 4; r++) c[nt][r] = 0.f;

    const int bswz = (tig ^ ((g >> 1) & 3));
#pragma unroll
    for (int kt = 0; kt < 4; kt++) {
        float4 nxta, nxtb;
        if (kt < 3) {
            nxta = __ldcs(&pA[4 * (kt + 1) + tig]);
            nxtb = __ldcs(&pB[4 * (kt + 1) + tig]);
        }
        unsigned ah[4], al[4];
        bf16_split2(cura.x, cura.y, ah[0], al[0]);
        bf16_split2(curb.x, curb.y, ah[1], al[1]);
        bf16_split2(cura.z, cura.w, ah[2], al[2]);
        bf16_split2(curb.z, curb.w, ah[3], al[3]);
        const int koff = 4 * (kt ^ (g & 1)) + bswz;
#pragma unroll
        for (int nt = 0; nt < 8; nt++) {
            uint4 b = Wg[(8 * nt + g) * 16 + koff];
            mma_bf16(c[nt], ah, b.x, b.y);   // Ah*Bh
            mma_bf16(c[nt], ah, b.z, b.w);   // Ah*Bl
            mma_bf16(c[nt], al, b.x, b.y);   // Al*Bh
        }
        cura = nxta; curb = nxtb;
    }

    // ---- epilogue: thread's chunk q = features 16q+4tig..+3 for rows eA,eB ----
    const float4* hsA = (const float4*)(g_hs + (size_t)sA * D_E);
    const float4* htA = (const float4*)(g_ht + (size_t)tA * D_E);
    const float4* hsB = (const float4*)(g_hs + (size_t)sB * D_E);
    const float4* htB = (const float4*)(g_ht + (size_t)tB * D_E);

    float ssA = 0.f, ssB = 0.f;
#pragma unroll
    for (int q = 0; q < 4; q++) {
        float4 H = hsA[4 * q + tig], T = htA[4 * q + tig];
        float v0 = (c[2*q  ][0] + H.x + T.x) * alphaA;
        float v1 = (c[2*q  ][1] + H.y + T.y) * alphaA;
        float v2 = (c[2*q+1][0] + H.z + T.z) * alphaA;
        float v3 = (c[2*q+1][1] + H.w + T.w) * alphaA;
        ssA += v0*v0 + v1*v1 + v2*v2 + v3*v3;
        c[2*q][0] = v0; c[2*q][1] = v1; c[2*q+1][0] = v2; c[2*q+1][1] = v3;
    }
#pragma unroll
    for (int q = 0; q < 4; q++) {
        float4 H = hsB[4 * q + tig], T = htB[4 * q + tig];
        float v0 = (c[2*q  ][2] + H.x + T.x) * alphaB;
        float v1 = (c[2*q  ][3] + H.y + T.y) * alphaB;
        float v2 = (c[2*q+1][2] + H.z + T.z) * alphaB;
        float v3 = (c[2*q+1][3] + H.w + T.w) * alphaB;
        ssB += v0*v0 + v1*v1 + v2*v2 + v3*v3;
        c[2*q][2] = v0; c[2*q][3] = v1; c[2*q+1][2] = v2; c[2*q+1][3] = v3;
    }

    ssA += __shfl_xor_sync(0xffffffffu, ssA, 1);
    ssB += __shfl_xor_sync(0xffffffffu, ssB, 1);
    ssA += __shfl_xor_sync(0xffffffffu, ssA, 2);
    ssB += __shfl_xor_sync(0xffffffffu, ssB, 2);
    const float rmsA = rsqrtf(ssA * (1.f / 64.f) + 1.1920929e-7f);
    const float rmsB = rsqrtf(ssB * (1.f / 64.f) + 1.1920929e-7f);

    if (vA) {
        float4* op = (float4*)(out + eA * D_E);
#pragma unroll
        for (int q = 0; q < 4; q++) {
            float4 w = __ldg(&((const float4*)norm_w)[4 * q + tig]);
            __stcs(&op[4 * q + tig],
                   make_float4(c[2*q][0]*rmsA*w.x, c[2*q][1]*rmsA*w.y,
                               c[2*q+1][0]*rmsA*w.z, c[2*q+1][1]*rmsA*w.w));
        }
    }
    if (vB) {
        float4* op = (float4*)(out + eB * D_E);
#pragma unroll
        for (int q = 0; q < 4; q++) {
            float4 w = __ldg(&((const float4*)norm_w)[4 * q + tig]);
            __stcs(&op[4 * q + tig],
                   make_float4(c[2*q][2]*rmsB*w.x, c[2*q][3]*rmsB*w.y,
                               c[2*q+1][2]*rmsB*w.z, c[2*q+1][3]*rmsB*w.w));
        }
    }
}

// ---------------- launch ----------------
extern "C" void kernel_launch(void* const* d_in, const int* in_sizes, int n_in,
                              void* d_out, int out_size) {
    const float* x_s    = (const float*)d_in[0];
    const float* x_t    = (const float*)d_in[1];
    const void*  eidx   = d_in[2];
    const float* ea     = (const float*)d_in[3];
    const float* W_src  = (const float*)d_in[5];
    const float* W_tgt  = (const float*)d_in[6];
    const float* W_edge = (const float*)d_in[7];
    const float* w_attn = (const float*)d_in[8];
    const float* norm_w = (const float*)d_in[9];
    float* out = (float*)d_out;

    prep_kernel<<<(N_NODE + 255) / 256, 256>>>(W_src, W_tgt, W_edge, w_attn);

    dim3 g1((N_NODE + 127) / 128, 2);
    node_proj_mma<<<g1, 256>>>(x_s, x_t, w_attn);

    long long score_threads = (long long)N_EDGE * 4;
    score_kernel<<<(unsigned)((score_threads + 255) / 256), 256>>>(ea, eidx);

    out_kernel<<<(N_EDGE + 127) / 128, 256>>>(ea, eidx, norm_w, out);
}

// round 14
// speedup vs baseline: 1.0586x; 1.0586x over previous
#include <cuda_runtime.h>
#include <math.h>

#define N_NODE  50000
#define N_EDGE  1000000
#define D_E     64
#define D_IN    128

// ---------------- device scratch (static; no allocations allowed) ----------------
__device__ float    g_hs[N_NODE * D_E];     // x_s @ W_src^T   (natural feature order)
__device__ float    g_ht[N_NODE * D_E];     // x_t @ W_tgt^T
__device__ float    g_as[N_NODE];           // hs . w_attn
__device__ float    g_at[N_NODE];           // ht . w_attn
__device__ float    g_v[D_E];               // W_edge^T @ w_attn
__device__ float    g_denom[N_NODE];        // softmax denominators per src
__device__ float    g_score[N_EDGE];        // post-leaky scores
// W_edge pre-split bf16 hi/lo groups for out_kernel (built in node_proj y==0)
__device__ uint4    g_Wg[D_E * 16];

// ---------------- helpers ----------------
__device__ __forceinline__ bool idx_is64(const void* p) {
    const long long* q = (const long long*)p;
    bool ok = true;
#pragma unroll
    for (int i = 0; i < 4; i++)
        ok = ok && ((unsigned long long)q[i] < (unsigned long long)N_NODE);
    return ok;
}
__device__ __forceinline__ int get_idx(const void* p, bool is64, size_t pos) {
    return is64 ? (int)((const long long*)p)[pos]
                : ((const int*)p)[pos];
}
// pack float pair -> bf16x2 hi plane + bf16x2 residual lo plane
__device__ __forceinline__ void bf16_split2(float x0, float x1, unsigned& hi, unsigned& lo) {
    unsigned h;
    asm("cvt.rn.bf16x2.f32 %0, %1, %2;" : "=r"(h) : "f"(x1), "f"(x0));
    float h0 = __uint_as_float(h << 16);
    float h1 = __uint_as_float(h & 0xFFFF0000u);
    unsigned l;
    asm("cvt.rn.bf16x2.f32 %0, %1, %2;" : "=r"(l) : "f"(x1 - h1), "f"(x0 - h0));
    hi = h; lo = l;
}
__device__ __forceinline__ void mma_bf16(float c[4], const unsigned a[4], unsigned b0, unsigned b1) {
    asm volatile(
        "mma.sync.aligned.m16n8k16.row.col.f32.bf16.bf16.f32 "
        "{%0,%1,%2,%3}, {%4,%5,%6,%7}, {%8,%9}, {%0,%1,%2,%3};"
        : "+f"(c[0]), "+f"(c[1]), "+f"(c[2]), "+f"(c[3])
        : "r"(a[0]), "r"(a[1]), "r"(a[2]), "r"(a[3]), "r"(b0), "r"(b1));
}
// feature permutation: logical MMA column n -> physical feature index.
__device__ __forceinline__ int fperm(int n) {
    return 16 * ((n >> 4) & 3) + 4 * ((n >> 1) & 3) + 2 * ((n >> 3) & 1) + (n & 1);
}

// ---------------- K1: node projections via bf16-split MMA + one-time init ----------------
// 128 nodes x 64 feats per block, K=128 (8 k-steps). blockIdx.y: 0=src, 1=tgt.
// Wsh built IN-BLOCK from the raw weights (no prep kernel / global staging).
// y==0 blocks also do one-time init: denom zero, g_v, g_Wg (all consumed by
// kernels launched strictly after this one).
__global__ void __launch_bounds__(256, 4) node_proj_mma(
    const float* __restrict__ x_s, const float* __restrict__ x_t,
    const float* __restrict__ W_src, const float* __restrict__ W_tgt,
    const float* __restrict__ W_edge, const float* __restrict__ w_attn) {
    __shared__ uint4 Wsh[D_E * 32];   // 32 KB

    const int tid  = threadIdx.x;
    const int lane = tid & 31, warp = tid >> 5;
    const int g = lane >> 2, tig = lane & 3;

    const float* x; float* hout; float* aout; const float* W;
    if (blockIdx.y == 0) { x = x_s; hout = g_hs; aout = g_as; W = W_src; }
    else                 { x = x_t; hout = g_ht; aout = g_at; W = W_tgt; }

    const int gid = blockIdx.x * 256 + tid;
    if (blockIdx.y == 0) {       // one-time init (used by later kernels only)
        if (gid < N_NODE) g_denom[gid] = 0.f;
        if (gid < D_E) {
            float s = 0.f;
#pragma unroll 8
            for (int j = 0; j < D_E; j++) s += W_edge[j * D_E + gid] * w_attn[j];
            g_v[gid] = s;
        }
        if (gid < D_E * 16) {    // build W_edge groups for out_kernel
            int n = gid >> 4, r = gid & 15;
            int kt = r >> 2, tg = r & 3;
            const float* wr = W_edge + (size_t)fperm(n) * D_E + 16 * kt + 4 * tg;
            unsigned h0, l0, h1, l1;
            bf16_split2(wr[0], wr[1], h0, l0);
            bf16_split2(wr[2], wr[3], h1, l1);
            int slot = n * 16 + 4 * (kt ^ (n & 1)) + (tg ^ ((n >> 1) & 3));
            g_Wg[slot] = make_uint4(h0, h1, l0, l1);
        }
    }

    // in-block W split: 8 groups per thread, straight from global W (L2 broadcast)
    for (int i = tid; i < D_E * 32; i += 256) {
        int n = i >> 5, r = i & 31;
        int kt = r >> 2, tg = r & 3;
        const float* wr = W + (size_t)fperm(n) * D_IN + 16 * kt + 4 * tg;
        float4 wv = *(const float4*)wr;
        unsigned h0, l0, h1, l1;
        bf16_split2(wv.x, wv.y, h0, l0);
        bf16_split2(wv.z, wv.w, h1, l1);
        int slot = n * 32 + 4 * (kt ^ (n & 1)) + (tg ^ ((n >> 1) & 3));
        Wsh[slot] = make_uint4(h0, h1, l0, l1);
    }

    const int n0 = blockIdx.x * 128;
    const int nA = n0 + warp * 16 + g;
    const int nB = nA + 8;
    const bool vA = (nA < N_NODE), vB = (nB < N_NODE);
    const size_t rA = (size_t)(vA ? nA : (N_NODE - 1));
    const size_t rB = (size_t)(vB ? nB : (N_NODE - 1));

    const float4* pA = (const float4*)(x + rA * D_IN);
    const float4* pB = (const float4*)(x + rB * D_IN);
    // rolling prefetch, phys k = 16kt + 4tig
    float4 cura = __ldcs(&pA[tig]);
    float4 curb = __ldcs(&pB[tig]);

    __syncthreads();

    float c[8][4];
#pragma unroll
    for (int nt = 0; nt < 8; nt++)
#pragma unroll
        for (int r = 0; r < 4; r++) c[nt][r] = 0.f;

    const int bswz = (tig ^ ((g >> 1) & 3));
#pragma unroll
    for (int kt = 0; kt < 8; kt++) {
        float4 nxta, nxtb;
        if (kt < 7) {
            nxta = __ldcs(&pA[4 * (kt + 1) + tig]);
            nxtb = __ldcs(&pB[4 * (kt + 1) + tig]);
        }
        unsigned ah[4], al[4];
        bf16_split2(cura.x, cura.y, ah[0], al[0]);
        bf16_split2(curb.x, curb.y, ah[1], al[1]);
        bf16_split2(cura.z, cura.w, ah[2], al[2]);
        bf16_split2(curb.z, curb.w, ah[3], al[3]);
        const int koff = 4 * (kt ^ (g & 1)) + bswz;
#pragma unroll
        for (int nt = 0; nt < 8; nt++) {
            uint4 b = Wsh[(8 * nt + g) * 32 + koff];
            mma_bf16(c[nt], ah, b.x, b.y);   // Ah*Bh
            mma_bf16(c[nt], ah, b.z, b.w);   // Ah*Bl
            mma_bf16(c[nt], al, b.x, b.y);   // Al*Bh
        }
        cura = nxta; curb = nxtb;
    }

    // ---- epilogue: write rows + attn dot. Thread's chunk q = feats 16q+4tig..+3.
    float avA = 0.f, avB = 0.f;
    if (vA) {
        float4* op = (float4*)(hout + (size_t)nA * D_E);
#pragma unroll
        for (int q = 0; q < 4; q++) {
            float4 w = __ldg(&((const float4*)w_attn)[4 * q + tig]);
            float4 r = make_float4(c[2*q][0], c[2*q][1], c[2*q+1][0], c[2*q+1][1]);
            avA += r.x * w.x + r.y * w.y + r.z * w.z + r.w * w.w;
            op[4 * q + tig] = r;
        }
    }
    if (vB) {
        float4* op = (float4*)(hout + (size_t)nB * D_E);
#pragma unroll
        for (int q = 0; q < 4; q++) {
            float4 w = __ldg(&((const float4*)w_attn)[4 * q + tig]);
            float4 r = make_float4(c[2*q][2], c[2*q][3], c[2*q+1][2], c[2*q+1][3]);
            avB += r.x * w.x + r.y * w.y + r.z * w.z + r.w * w.w;
            op[4 * q + tig] = r;
        }
    }
    avA += __shfl_xor_sync(0xffffffffu, avA, 1);
    avB += __shfl_xor_sync(0xffffffffu, avB, 1);
    avA += __shfl_xor_sync(0xffffffffu, avA, 2);
    avB += __shfl_xor_sync(0xffffffffu, avB, 2);
    if (tig == 0) {
        if (vA) aout[nA] = avA;
        if (vB) aout[nB] = avB;
    }
}

// ---------------- K2: per-edge score + FUSED softmax denominator ----------------
// __ldcs streaming loads: protect L2 residency for the hs/ht gather tables
// (R13 lesson: default-policy here evicts them and slows out_kernel).
__global__ void __launch_bounds__(256) score_kernel(
    const float* __restrict__ edge_attr, const void* __restrict__ eidx) {
    __shared__ float v[D_E];
    if (threadIdx.x < D_E) v[threadIdx.x] = g_v[threadIdx.x];
    __syncthreads();

    long long t = (long long)blockIdx.x * 256 + threadIdx.x;
    long long e = t >> 2;
    int q = (int)(t & 3);
    if (e >= N_EDGE) return;

    const float4* row = (const float4*)(edge_attr + e * D_E);
    float p = 0.f;
#pragma unroll
    for (int i = 0; i < 4; i++) {
        float4 av = __ldcs(&row[q + 4 * i]);
        float4 vv = *(const float4*)&v[4 * (q + 4 * i)];
        p += av.x * vv.x + av.y * vv.y + av.z * vv.z + av.w * vv.w;
    }
    p += __shfl_xor_sync(0xffffffffu, p, 1);
    p += __shfl_xor_sync(0xffffffffu, p, 2);
    if (q == 0) {
        bool is64 = idx_is64(eidx);
        int src = get_idx(eidx, is64, (size_t)e);
        int tgt = get_idx(eidx, is64, (size_t)N_EDGE + e);
        float s = p + g_as[src] + g_at[tgt];
        s = (s >= 0.f) ? s : 0.2f * s;
        g_score[e] = s;
        atomicAdd(&g_denom[src], __expf(s));
    }
}

// ---------------- K4: bf16-split tensor GEMM + gather + softmax + RMSNorm ----------------
// Forward block order (R13's reversal regressed). All global accesses 128-bit.
__global__ void __launch_bounds__(256, 4) out_kernel(
    const float* __restrict__ edge_attr, const void* __restrict__ eidx,
    const float* __restrict__ norm_w, float* __restrict__ out) {
    __shared__ uint4 Wg[D_E * 16];   // 16 KB

    const bool is64 = idx_is64(eidx);
    const int tid  = threadIdx.x;
    const int lane = tid & 31, warp = tid >> 5;
    const int g = lane >> 2, tig = lane & 3;

    for (int i = tid; i < D_E * 16; i += 256) Wg[i] = g_Wg[i];

    const long long e0 = (long long)blockIdx.x * 128;
    const long long eA = e0 + warp * 16 + g;
    const long long eB = eA + 8;
    const bool vA = (eA < N_EDGE), vB = (eB < N_EDGE);
    const size_t rA = (size_t)(vA ? eA : (N_EDGE - 1));
    const size_t rB = (size_t)(vB ? eB : (N_EDGE - 1));

    // ---- prefetch epilogue metadata early (hide latency under MMA) ----
    const int sA = get_idx(eidx, is64, rA);
    const int tA = get_idx(eidx, is64, (size_t)N_EDGE + rA);
    const int sB = get_idx(eidx, is64, rB);
    const int tB = get_idx(eidx, is64, (size_t)N_EDGE + rB);
    float aAv = 0.f, aBv = 0.f;
    if (tig == 0) {
        aAv = __expf(g_score[rA]) / g_denom[sA];
        aBv = __expf(g_score[rB]) / g_denom[sB];
    }

    const float4* pA = (const float4*)(edge_attr + rA * D_E);
    const float4* pB = (const float4*)(edge_attr + rB * D_E);
    // rolling prefetch: stage kt=0
    float4 cura = __ldcs(&pA[tig]);
    float4 curb = __ldcs(&pB[tig]);

    const float alphaA = __shfl_sync(0xffffffffu, aAv, lane & 28);
    const float alphaB = __shfl_sync(0xffffffffu, aBv, lane & 28);

    __syncthreads();

    // ---- MMA mainloop ----
    float c[8][4];
#pragma unroll
    for (int nt = 0; nt < 8; nt++)
#pragma unroll
        for (int r = 0; r < 4; r++) c[nt][r] = 0.f;

    const int bswz = (tig ^ ((g >> 1) & 3));
#pragma unroll
    for (int kt = 0; kt < 4; kt++) {
        float4 nxta, nxtb;
        if (kt < 3) {
            nxta = __ldcs(&pA[4 * (kt + 1) + tig]);
            nxtb = __ldcs(&pB[4 * (kt + 1) + tig]);
        }
        unsigned ah[4], al[4];
        bf16_split2(cura.x, cura.y, ah[0], al[0]);
        bf16_split2(curb.x, curb.y, ah[1], al[1]);
        bf16_split2(cura.z, cura.w, ah[2], al[2]);
        bf16_split2(curb.z, curb.w, ah[3], al[3]);
        const int koff = 4 * (kt ^ (g & 1)) + bswz;
#pragma unroll
        for (int nt = 0; nt < 8; nt++) {
            uint4 b = Wg[(8 * nt + g) * 16 + koff];
            mma_bf16(c[nt], ah, b.x, b.y);   // Ah*Bh
            mma_bf16(c[nt], ah, b.z, b.w);   // Ah*Bl
            mma_bf16(c[nt], al, b.x, b.y);   // Al*Bh
        }
        cura = nxta; curb = nxtb;
    }

    // ---- epilogue: thread's chunk q = features 16q+4tig..+3 for rows eA,eB ----
    const float4* hsA = (const float4*)(g_hs + (size_t)sA * D_E);
    const float4* htA = (const float4*)(g_ht + (size_t)tA * D_E);
    const float4* hsB = (const float4*)(g_hs + (size_t)sB * D_E);
    const float4* htB = (const float4*)(g_ht + (size_t)tB * D_E);

    float ssA = 0.f, ssB = 0.f;
#pragma unroll
    for (int q = 0; q < 4; q++) {
        float4 H = hsA[4 * q + tig], T = htA[4 * q + tig];
        float v0 = (c[2*q  ][0] + H.x + T.x) * alphaA;
        float v1 = (c[2*q  ][1] + H.y + T.y) * alphaA;
        float v2 = (c[2*q+1][0] + H.z + T.z) * alphaA;
        float v3 = (c[2*q+1][1] + H.w + T.w) * alphaA;
        ssA += v0*v0 + v1*v1 + v2*v2 + v3*v3;
        c[2*q][0] = v0; c[2*q][1] = v1; c[2*q+1][0] = v2; c[2*q+1][1] = v3;
    }
#pragma unroll
    for (int q = 0; q < 4; q++) {
        float4 H = hsB[4 * q + tig], T = htB[4 * q + tig];
        float v0 = (c[2*q  ][2] + H.x + T.x) * alphaB;
        float v1 = (c[2*q  ][3] + H.y + T.y) * alphaB;
        float v2 = (c[2*q+1][2] + H.z + T.z) * alphaB;
        float v3 = (c[2*q+1][3] + H.w + T.w) * alphaB;
        ssB += v0*v0 + v1*v1 + v2*v2 + v3*v3;
        c[2*q][2] = v0; c[2*q][3] = v1; c[2*q+1][2] = v2; c[2*q+1][3] = v3;
    }

    ssA += __shfl_xor_sync(0xffffffffu, ssA, 1);
    ssB += __shfl_xor_sync(0xffffffffu, ssB, 1);
    ssA += __shfl_xor_sync(0xffffffffu, ssA, 2);
    ssB += __shfl_xor_sync(0xffffffffu, ssB, 2);
    const float rmsA = rsqrtf(ssA * (1.f / 64.f) + 1.1920929e-7f);
    const float rmsB = rsqrtf(ssB * (1.f / 64.f) + 1.1920929e-7f);

    if (vA) {
        float4* op = (float4*)(out + eA * D_E);
#pragma unroll
        for (int q = 0; q < 4; q++) {
            float4 w = __ldg(&((const float4*)norm_w)[4 * q + tig]);
            __stcs(&op[4 * q + tig],
                   make_float4(c[2*q][0]*rmsA*w.x, c[2*q][1]*rmsA*w.y,
                               c[2*q+1][0]*rmsA*w.z, c[2*q+1][1]*rmsA*w.w));
        }
    }
    if (vB) {
        float4* op = (float4*)(out + eB * D_E);
#pragma unroll
        for (int q = 0; q < 4; q++) {
            float4 w = __ldg(&((const float4*)norm_w)[4 * q + tig]);
            __stcs(&op[4 * q + tig],
                   make_float4(c[2*q][2]*rmsB*w.x, c[2*q][3]*rmsB*w.y,
                               c[2*q+1][2]*rmsB*w.z, c[2*q+1][3]*rmsB*w.w));
        }
    }
}

// ---------------- launch ----------------
extern "C" void kernel_launch(void* const* d_in, const int* in_sizes, int n_in,
                              void* d_out, int out_size) {
    const float* x_s    = (const float*)d_in[0];
    const float* x_t    = (const float*)d_in[1];
    const void*  eidx   = d_in[2];
    const float* ea     = (const float*)d_in[3];
    const float* W_src  = (const float*)d_in[5];
    const float* W_tgt  = (const float*)d_in[6];
    const float* W_edge = (const float*)d_in[7];
    const float* w_attn = (const float*)d_in[8];
    const float* norm_w = (const float*)d_in[9];
    float* out = (float*)d_out;

    dim3 g1((N_NODE + 127) / 128, 2);
    node_proj_mma<<<g1, 256>>>(x_s, x_t, W_src, W_tgt, W_edge, w_attn);

    long long score_threads = (long long)N_EDGE * 4;
    score_kernel<<<(unsigned)((score_threads + 255) / 256), 256>>>(ea, eidx);

    out_kernel<<<(N_EDGE + 127) / 128, 256>>>(ea, eidx, norm_w, out);
}